// round 1
// baseline (speedup 1.0000x reference)
#include <cuda_runtime.h>
#include <cuda_bf16.h>
#include <cstdint>

// Problem constants (from reference): N=100000, E=1600000, NIN=NOUT=128.
// Scratch (allocation-free rule: __device__ globals).
#define MAX_N 100000
#define F 128

__device__ float g_deg[MAX_N];        // degree (incl. self loop) -> dinv in place
__device__ float g_h[(size_t)MAX_N * F];  // h = X @ W

// ---------------------------------------------------------------------------
// 1) deg init to 1.0 (self loop)
__global__ void k_init_deg(int n) {
    int i = blockIdx.x * blockDim.x + threadIdx.x;
    if (i < n) g_deg[i] = 1.0f;
}

// 2) deg count over dst
__global__ void k_count(const int* __restrict__ dst, int e) {
    int i = blockIdx.x * blockDim.x + threadIdx.x;
    if (i < e) atomicAdd(&g_deg[dst[i]], 1.0f);
}

// 3) dinv = rsqrt(deg)  (deg >= 1 always)
__global__ void k_dinv(int n) {
    int i = blockIdx.x * blockDim.x + threadIdx.x;
    if (i < n) g_deg[i] = rsqrtf(g_deg[i]);
}

// ---------------------------------------------------------------------------
// 4) GEMM: h[r][c] = sum_k x[r][k] * W[k][c].  W fully resident in smem (64KB).
//    256 threads: c = tid & 127, row-half = tid >> 7; each thread does 4 rows
//    of an 8-row tile, grid-stride over row tiles.
__global__ __launch_bounds__(256, 3) void k_gemm(const float* __restrict__ x,
                                                 const float* __restrict__ W,
                                                 int nrows) {
    extern __shared__ float sm[];
    float* Ws = sm;                 // 128*128
    float4* Ws4 = (float4*)Ws;
    float* xs = sm + F * F;         // 8*128
    float4* xs4 = (float4*)xs;

    const float4* W4 = (const float4*)W;
    for (int i = threadIdx.x; i < F * F / 4; i += 256) Ws4[i] = W4[i];
    __syncthreads();

    const int c  = threadIdx.x & 127;
    const int rh = threadIdx.x >> 7;  // 0..1 -> rows rh*4 .. rh*4+3

    for (long long row0 = (long long)blockIdx.x * 8; row0 < nrows;
         row0 += (long long)gridDim.x * 8) {
        // load 8 rows of x (1024 floats = 256 float4)
        {
            int i = threadIdx.x;          // i -> row i>>5, chunk i&31
            int r = i >> 5, k4 = i & 31;
            long long row = row0 + r;
            float4 v = make_float4(0.f, 0.f, 0.f, 0.f);
            if (row < nrows) v = ((const float4*)(x + row * F))[k4];
            xs4[i] = v;
        }
        __syncthreads();

        float acc0 = 0.f, acc1 = 0.f, acc2 = 0.f, acc3 = 0.f;
        const int rb = rh * 4;
#pragma unroll
        for (int k4 = 0; k4 < 32; k4++) {
            float4 x0 = xs4[(rb + 0) * 32 + k4];
            float4 x1 = xs4[(rb + 1) * 32 + k4];
            float4 x2 = xs4[(rb + 2) * 32 + k4];
            float4 x3 = xs4[(rb + 3) * 32 + k4];
            float w0 = Ws[(4 * k4 + 0) * F + c];
            float w1 = Ws[(4 * k4 + 1) * F + c];
            float w2 = Ws[(4 * k4 + 2) * F + c];
            float w3 = Ws[(4 * k4 + 3) * F + c];
            acc0 += x0.x * w0 + x0.y * w1 + x0.z * w2 + x0.w * w3;
            acc1 += x1.x * w0 + x1.y * w1 + x1.z * w2 + x1.w * w3;
            acc2 += x2.x * w0 + x2.y * w1 + x2.z * w2 + x2.w * w3;
            acc3 += x3.x * w0 + x3.y * w1 + x3.z * w2 + x3.w * w3;
        }
        long long r0 = row0 + rb;
        if (r0 + 0 < nrows) g_h[(r0 + 0) * F + c] = acc0;
        if (r0 + 1 < nrows) g_h[(r0 + 1) * F + c] = acc1;
        if (r0 + 2 < nrows) g_h[(r0 + 2) * F + c] = acc2;
        if (r0 + 3 < nrows) g_h[(r0 + 3) * F + c] = acc3;
        __syncthreads();
    }
}

// ---------------------------------------------------------------------------
// 5) out = b + h * dinv^2  (self-loop message), vectorized float4
__global__ void k_selfout(float* __restrict__ out, const float* __restrict__ b,
                          int n) {
    int i = blockIdx.x * blockDim.x + threadIdx.x;   // index into n*32 float4s
    int total = n * (F / 4);
    if (i >= total) return;
    int node = i >> 5;
    int lane = i & 31;
    float di = g_deg[node];         // dinv
    float coef = di * di;
    float4 hv = ((const float4*)g_h)[i];
    float4 bv = ((const float4*)b)[lane];
    float4 o;
    o.x = bv.x + hv.x * coef;
    o.y = bv.y + hv.y * coef;
    o.z = bv.z + hv.z * coef;
    o.w = bv.w + hv.w * coef;
    ((float4*)out)[i] = o;
}

// ---------------------------------------------------------------------------
// 6) edge scatter: one warp per edge, each lane does one float4 red.add
__global__ __launch_bounds__(256) void k_scatter(const int* __restrict__ src,
                                                 const int* __restrict__ dst,
                                                 float* __restrict__ out,
                                                 int e) {
    int warp = blockIdx.x * 8 + (threadIdx.x >> 5);
    if (warp >= e) return;
    int lane = threadIdx.x & 31;
    int s = src[warp];
    int d = dst[warp];
    float coef = g_deg[s] * g_deg[d];   // dinv[s]*dinv[d]
    float4 hv = ((const float4*)g_h)[(long long)s * 32 + lane];
    float4 m;
    m.x = hv.x * coef; m.y = hv.y * coef; m.z = hv.z * coef; m.w = hv.w * coef;
    float* p = out + (long long)d * F + lane * 4;
    asm volatile("red.global.add.v4.f32 [%0], {%1, %2, %3, %4};"
                 :: "l"(p), "f"(m.x), "f"(m.y), "f"(m.z), "f"(m.w)
                 : "memory");
}

// ---------------------------------------------------------------------------
extern "C" void kernel_launch(void* const* d_in, const int* in_sizes, int n_in,
                              void* d_out, int out_size) {
    const float* x  = (const float*)d_in[0];
    const int*   ei = (const int*)d_in[1];
    // d_in[2] = edge_attr (ignored by reference)
    const float* W  = (const float*)d_in[3];
    const float* b  = (const float*)d_in[4];
    float* out = (float*)d_out;

    int n = in_sizes[0] / F;       // 100000
    int e = in_sizes[1] / 2;       // 1600000
    const int* src = ei;
    const int* dst = ei + e;

    // degree / dinv
    k_init_deg<<<(n + 255) / 256, 256>>>(n);
    k_count<<<(e + 255) / 256, 256>>>(dst, e);
    k_dinv<<<(n + 255) / 256, 256>>>(n);

    // h = X @ W
    static bool attr_done = false;
    if (!attr_done) {
        cudaFuncSetAttribute(k_gemm, cudaFuncAttributeMaxDynamicSharedMemorySize,
                             (F * F + 8 * F) * (int)sizeof(float));
        attr_done = true;
    }
    int smem = (F * F + 8 * F) * (int)sizeof(float);   // 68 KB
    k_gemm<<<444, 256, smem>>>(x, W, n);

    // out = b + self-loop message
    int tot4 = n * (F / 4);
    k_selfout<<<(tot4 + 255) / 256, 256>>>(out, b, n);

    // edge messages
    k_scatter<<<(e + 7) / 8, 256>>>(src, dst, out, e);
}

// round 2
// speedup vs baseline: 1.6769x; 1.6769x over previous
#include <cuda_runtime.h>
#include <cuda_bf16.h>
#include <cstdint>

#define MAX_N 100000
#define MAX_E 1600000
#define F 128
#define SCAN_CHUNK 512
#define MAX_BLK ((MAX_N + SCAN_CHUNK - 1) / SCAN_CHUNK)   // 196

// Scratch (__device__ globals; no allocations allowed)
__device__ float g_h[(size_t)MAX_N * F];   // h = X @ W
__device__ float g_dinv[MAX_N];
__device__ int   g_cnt[MAX_N];             // in-degree (excl self loop)
__device__ int   g_start[MAX_N];           // CSR row start
__device__ int   g_cursor[MAX_N];          // fill cursor
__device__ int   g_esrc[MAX_E];            // src ids sorted by dst
__device__ int   g_bsum[MAX_BLK];          // scan block sums

// ---------------------------------------------------------------------------
__global__ void k_zero(int n) {
    int i = blockIdx.x * blockDim.x + threadIdx.x;
    if (i < n) g_cnt[i] = 0;
}

__global__ void k_hist(const int* __restrict__ dst, int e) {
    int i = blockIdx.x * blockDim.x + threadIdx.x;
    if (i < e) atomicAdd(&g_cnt[dst[i]], 1);
}

// per-chunk sums
__global__ void k_scan1(int n) {
    __shared__ int wsum[16];
    int b = blockIdx.x;
    int i = b * SCAN_CHUNK + threadIdx.x;
    int v = (i < n) ? g_cnt[i] : 0;
    // warp reduce
    for (int o = 16; o > 0; o >>= 1) v += __shfl_down_sync(~0u, v, o);
    int lane = threadIdx.x & 31, wid = threadIdx.x >> 5;
    if (lane == 0) wsum[wid] = v;
    __syncthreads();
    if (wid == 0) {
        int s = (lane < (SCAN_CHUNK / 32)) ? wsum[lane] : 0;
        for (int o = 16; o > 0; o >>= 1) s += __shfl_down_sync(~0u, s, o);
        if (lane == 0) g_bsum[b] = s;
    }
}

// exclusive scan of block sums (nblk <= 512, single block)
__global__ void k_scan2(int nblk) {
    __shared__ int wsum[16];
    int t = threadIdx.x;
    int v = (t < nblk) ? g_bsum[t] : 0;
    int lane = t & 31, wid = t >> 5;
    int x = v;
    for (int o = 1; o < 32; o <<= 1) {
        int y = __shfl_up_sync(~0u, x, o);
        if (lane >= o) x += y;
    }
    if (lane == 31) wsum[wid] = x;
    __syncthreads();
    if (wid == 0) {
        int w = (lane < 16) ? wsum[lane] : 0;
        for (int o = 1; o < 16; o <<= 1) {
            int y = __shfl_up_sync(~0u, w, o);
            if (lane >= o) w += y;
        }
        if (lane < 16) wsum[lane] = w;
    }
    __syncthreads();
    int incl = x + (wid ? wsum[wid - 1] : 0);
    if (t < nblk) g_bsum[t] = incl - v;   // exclusive
}

// per-chunk exclusive scan + offset; also dinv, cursor init
__global__ void k_scan3(int n) {
    __shared__ int wsum[16];
    int b = blockIdx.x;
    int i = b * SCAN_CHUNK + threadIdx.x;
    int v = (i < n) ? g_cnt[i] : 0;
    int lane = threadIdx.x & 31, wid = threadIdx.x >> 5;
    int x = v;
    for (int o = 1; o < 32; o <<= 1) {
        int y = __shfl_up_sync(~0u, x, o);
        if (lane >= o) x += y;
    }
    if (lane == 31) wsum[wid] = x;
    __syncthreads();
    if (wid == 0) {
        int w = (lane < (SCAN_CHUNK / 32)) ? wsum[lane] : 0;
        for (int o = 1; o < 16; o <<= 1) {
            int y = __shfl_up_sync(~0u, w, o);
            if (lane >= o) w += y;
        }
        if (lane < (SCAN_CHUNK / 32)) wsum[lane] = w;
    }
    __syncthreads();
    int excl = x - v + (wid ? wsum[wid - 1] : 0);
    if (i < n) {
        int s = excl + g_bsum[b];
        g_start[i] = s;
        g_cursor[i] = s;
        g_dinv[i] = rsqrtf((float)(v + 1));   // +1 self loop
    }
}

__global__ void k_fill(const int* __restrict__ src, const int* __restrict__ dst,
                       int e) {
    int i = blockIdx.x * blockDim.x + threadIdx.x;
    if (i < e) {
        int p = atomicAdd(&g_cursor[dst[i]], 1);
        g_esrc[p] = src[i];
    }
}

// ---------------------------------------------------------------------------
// GEMM: h = X @ W.  Block: 256 thr, tile 64 rows x 128 cols.
// Thread: 8 rows x 4 cols (outer-product), W + x tiles in smem.
__global__ __launch_bounds__(256, 2) void k_gemm(const float* __restrict__ x,
                                                 const float* __restrict__ W,
                                                 int nrows) {
    extern __shared__ float sm[];
    float4* Ws4 = (float4*)sm;               // 128 x 32 float4 (64KB)
    float4* xs4 = (float4*)(sm + F * F);     // 64 x 32 float4 (32KB)

    const float4* W4 = (const float4*)W;
    for (int i = threadIdx.x; i < F * F / 4; i += 256) Ws4[i] = W4[i];

    const int row0 = blockIdx.x * 64;
    const float4* x4 = (const float4*)x;
    // load 64 rows of x
    for (int i = threadIdx.x; i < 64 * 32; i += 256) {
        int r = i >> 5, k4 = i & 31;
        float4 v = make_float4(0.f, 0.f, 0.f, 0.f);
        if (row0 + r < nrows) v = x4[(long long)(row0 + r) * 32 + k4];
        xs4[i] = v;
    }
    __syncthreads();

    const int l = threadIdx.x & 31;   // cols 4l..4l+3
    const int w = threadIdx.x >> 5;   // rows w*8..w*8+7

    float4 acc[8];
#pragma unroll
    for (int j = 0; j < 8; j++) acc[j] = make_float4(0.f, 0.f, 0.f, 0.f);

#pragma unroll 4
    for (int k4 = 0; k4 < 32; k4++) {
        float4 wv0 = Ws4[(4 * k4 + 0) * 32 + l];
        float4 wv1 = Ws4[(4 * k4 + 1) * 32 + l];
        float4 wv2 = Ws4[(4 * k4 + 2) * 32 + l];
        float4 wv3 = Ws4[(4 * k4 + 3) * 32 + l];
#pragma unroll
        for (int j = 0; j < 8; j++) {
            float4 xv = xs4[(w * 8 + j) * 32 + k4];
            acc[j].x += xv.x * wv0.x + xv.y * wv1.x + xv.z * wv2.x + xv.w * wv3.x;
            acc[j].y += xv.x * wv0.y + xv.y * wv1.y + xv.z * wv2.y + xv.w * wv3.y;
            acc[j].z += xv.x * wv0.z + xv.y * wv1.z + xv.z * wv2.z + xv.w * wv3.z;
            acc[j].w += xv.x * wv0.w + xv.y * wv1.w + xv.z * wv2.w + xv.w * wv3.w;
        }
    }

    float4* h4 = (float4*)g_h;
#pragma unroll
    for (int j = 0; j < 8; j++) {
        int r = row0 + w * 8 + j;
        if (r < nrows) h4[(long long)r * 32 + l] = acc[j];
    }
}

// ---------------------------------------------------------------------------
// Aggregate: one warp per dst node. acc = sum_{edges} h[src]*dinv[s]*dinv[d]
//            + h[d]*dinv[d]^2 + b.  No atomics.
__global__ __launch_bounds__(256) void k_agg(const float* __restrict__ bias,
                                             float* __restrict__ out, int n) {
    int node = blockIdx.x * 8 + (threadIdx.x >> 5);
    if (node >= n) return;
    int lane = threadIdx.x & 31;

    const float4* h4 = (const float4*)g_h;
    float dd = g_dinv[node];

    float4 acc = h4[(long long)node * 32 + lane];
    float cself = dd * dd;
    acc.x *= cself; acc.y *= cself; acc.z *= cself; acc.w *= cself;

    int j = g_start[node];
    int end = j + g_cnt[node];

    for (; j + 1 < end; j += 2) {
        int sA = g_esrc[j];
        int sB = g_esrc[j + 1];
        float4 a = h4[(long long)sA * 32 + lane];
        float4 c = h4[(long long)sB * 32 + lane];
        float cA = g_dinv[sA] * dd;
        float cB = g_dinv[sB] * dd;
        acc.x += a.x * cA + c.x * cB;
        acc.y += a.y * cA + c.y * cB;
        acc.z += a.z * cA + c.z * cB;
        acc.w += a.w * cA + c.w * cB;
    }
    if (j < end) {
        int sA = g_esrc[j];
        float cA = g_dinv[sA] * dd;
        float4 a = h4[(long long)sA * 32 + lane];
        acc.x += a.x * cA; acc.y += a.y * cA; acc.z += a.z * cA; acc.w += a.w * cA;
    }

    float4 bv = ((const float4*)bias)[lane];
    acc.x += bv.x; acc.y += bv.y; acc.z += bv.z; acc.w += bv.w;
    ((float4*)out)[(long long)node * 32 + lane] = acc;
}

// ---------------------------------------------------------------------------
extern "C" void kernel_launch(void* const* d_in, const int* in_sizes, int n_in,
                              void* d_out, int out_size) {
    const float* x  = (const float*)d_in[0];
    const int*   ei = (const int*)d_in[1];
    const float* W  = (const float*)d_in[3];
    const float* b  = (const float*)d_in[4];
    float* out = (float*)d_out;

    int n = in_sizes[0] / F;     // 100000
    int e = in_sizes[1] / 2;     // 1600000
    const int* src = ei;
    const int* dst = ei + e;

    int nblk = (n + SCAN_CHUNK - 1) / SCAN_CHUNK;

    // CSR build + dinv
    k_zero <<<(n + 255) / 256, 256>>>(n);
    k_hist <<<(e + 255) / 256, 256>>>(dst, e);
    k_scan1<<<nblk, SCAN_CHUNK>>>(n);
    k_scan2<<<1, 512>>>(nblk);
    k_scan3<<<nblk, SCAN_CHUNK>>>(n);
    k_fill <<<(e + 255) / 256, 256>>>(src, dst, e);

    // GEMM
    static bool attr_done = false;
    if (!attr_done) {
        cudaFuncSetAttribute(k_gemm, cudaFuncAttributeMaxDynamicSharedMemorySize,
                             (F * F + 64 * F) * (int)sizeof(float));
        attr_done = true;
    }
    int smem = (F * F + 64 * F) * (int)sizeof(float);   // 96 KB
    k_gemm<<<(n + 63) / 64, 256, smem>>>(x, W, n);

    // Aggregate (self-loop + bias fused)
    k_agg<<<(n + 7) / 8, 256>>>(b, out, n);
}

// round 5
// speedup vs baseline: 2.0436x; 1.2187x over previous
#include <cuda_runtime.h>
#include <cuda_fp16.h>
#include <cstdint>

#define MAX_N 100000
#define MAX_E 1600000
#define F 128
#define SCAN_CHUNK 512
#define MAX_BLK ((MAX_N + SCAN_CHUNK - 1) / SCAN_CHUNK)
#define PITCH 132   // 128 + 4 pad: conflict-free mma frag loads

// Scratch (__device__ globals; no allocations allowed)
__device__ __half2 g_h16[(size_t)MAX_N * (F / 2)];  // h*dinv, fp16 (25.6MB)
__device__ float g_dinv[MAX_N];
__device__ int   g_cnt[MAX_N];
__device__ int   g_start[MAX_N];
__device__ int   g_cursor[MAX_N];
__device__ int   g_esrc[MAX_E];
__device__ int   g_bsum[MAX_BLK];

// ---------------------------------------------------------------------------
__global__ void k_zero(int n) {
    int i = blockIdx.x * blockDim.x + threadIdx.x;
    if (i < n) g_cnt[i] = 0;
}

__global__ void k_hist(const int* __restrict__ dst, int e) {
    int i = blockIdx.x * blockDim.x + threadIdx.x;
    if (i < e) atomicAdd(&g_cnt[dst[i]], 1);
}

__global__ void k_scan1(int n) {
    __shared__ int wsum[16];
    int b = blockIdx.x;
    int i = b * SCAN_CHUNK + threadIdx.x;
    int v = (i < n) ? g_cnt[i] : 0;
    for (int o = 16; o > 0; o >>= 1) v += __shfl_down_sync(~0u, v, o);
    int lane = threadIdx.x & 31, wid = threadIdx.x >> 5;
    if (lane == 0) wsum[wid] = v;
    __syncthreads();
    if (wid == 0) {
        int s = (lane < (SCAN_CHUNK / 32)) ? wsum[lane] : 0;
        for (int o = 16; o > 0; o >>= 1) s += __shfl_down_sync(~0u, s, o);
        if (lane == 0) g_bsum[b] = s;
    }
}

__global__ void k_scan2(int nblk) {
    __shared__ int wsum[16];
    int t = threadIdx.x;
    int v = (t < nblk) ? g_bsum[t] : 0;
    int lane = t & 31, wid = t >> 5;
    int x = v;
    for (int o = 1; o < 32; o <<= 1) {
        int y = __shfl_up_sync(~0u, x, o);
        if (lane >= o) x += y;
    }
    if (lane == 31) wsum[wid] = x;
    __syncthreads();
    if (wid == 0) {
        int w = (lane < 16) ? wsum[lane] : 0;
        for (int o = 1; o < 16; o <<= 1) {
            int y = __shfl_up_sync(~0u, w, o);
            if (lane >= o) w += y;
        }
        if (lane < 16) wsum[lane] = w;
    }
    __syncthreads();
    int incl = x + (wid ? wsum[wid - 1] : 0);
    if (t < nblk) g_bsum[t] = incl - v;
}

__global__ void k_scan3(int n) {
    __shared__ int wsum[16];
    int b = blockIdx.x;
    int i = b * SCAN_CHUNK + threadIdx.x;
    int v = (i < n) ? g_cnt[i] : 0;
    int lane = threadIdx.x & 31, wid = threadIdx.x >> 5;
    int x = v;
    for (int o = 1; o < 32; o <<= 1) {
        int y = __shfl_up_sync(~0u, x, o);
        if (lane >= o) x += y;
    }
    if (lane == 31) wsum[wid] = x;
    __syncthreads();
    if (wid == 0) {
        int w = (lane < (SCAN_CHUNK / 32)) ? wsum[lane] : 0;
        for (int o = 1; o < 16; o <<= 1) {
            int y = __shfl_up_sync(~0u, w, o);
            if (lane >= o) w += y;
        }
        if (lane < (SCAN_CHUNK / 32)) wsum[lane] = w;
    }
    __syncthreads();
    int excl = x - v + (wid ? wsum[wid - 1] : 0);
    if (i < n) {
        int s = excl + g_bsum[b];
        g_start[i] = s;
        g_cursor[i] = s;
        g_dinv[i] = rsqrtf((float)(v + 1));
    }
}

__global__ void k_fill(const int* __restrict__ src, const int* __restrict__ dst,
                       int e) {
    int i = blockIdx.x * blockDim.x + threadIdx.x;
    if (i < e) {
        int p = atomicAdd(&g_cursor[dst[i]], 1);
        g_esrc[p] = src[i];
    }
}

// ---------------------------------------------------------------------------
__device__ __forceinline__ unsigned cvt_tf32(float f) {
    unsigned u;
    asm("cvt.rna.tf32.f32 %0, %1;" : "=r"(u) : "f"(f));
    return u;
}

// GEMM via HMMA tf32: h16s = (x @ W) * dinv[row], stored fp16.
// Block 256 thr (8 warps), 128 rows/block; warp = 16 rows.
// smem: Wt (tf32 bits, transposed, padded) + xs (tf32 bits, padded).
__global__ __launch_bounds__(256, 1) void k_gemm(const float* __restrict__ x,
                                                 const float* __restrict__ W,
                                                 int n) {
    extern __shared__ float sm[];
    float* Wt = sm;                   // Wt[nn*PITCH + k] = tf32(W[k][nn])
    float* xs = sm + 128 * PITCH;     // xs[r*PITCH + k]  = tf32(x[row0+r][k])

    const int tid = threadIdx.x;
    // Stage W transposed + tf32-converted
    for (int i = tid; i < 128 * 32; i += 256) {
        int k = i >> 5, c4 = (i & 31) * 4;
        float4 v = ((const float4*)W)[i];
        Wt[(c4 + 0) * PITCH + k] = __uint_as_float(cvt_tf32(v.x));
        Wt[(c4 + 1) * PITCH + k] = __uint_as_float(cvt_tf32(v.y));
        Wt[(c4 + 2) * PITCH + k] = __uint_as_float(cvt_tf32(v.z));
        Wt[(c4 + 3) * PITCH + k] = __uint_as_float(cvt_tf32(v.w));
    }
    const int row0 = blockIdx.x * 128;
    for (int i = tid; i < 128 * 32; i += 256) {
        int r = i >> 5, k4 = i & 31;
        float4 v = make_float4(0.f, 0.f, 0.f, 0.f);
        if (row0 + r < n) v = ((const float4*)x)[(long long)(row0 + r) * 32 + k4];
        v.x = __uint_as_float(cvt_tf32(v.x));
        v.y = __uint_as_float(cvt_tf32(v.y));
        v.z = __uint_as_float(cvt_tf32(v.z));
        v.w = __uint_as_float(cvt_tf32(v.w));
        *(float4*)&xs[r * PITCH + k4 * 4] = v;
    }
    __syncthreads();

    const int warp = tid >> 5, lane = tid & 31;
    const int g = lane >> 2, t = lane & 3;
    const int rbase = warp * 16;

    // Hoist all A fragments (16 k-tiles x 4 regs)
    unsigned a[16][4];
#pragma unroll
    for (int kt = 0; kt < 16; kt++) {
        a[kt][0] = __float_as_uint(xs[(rbase + g) * PITCH + kt * 8 + t]);
        a[kt][1] = __float_as_uint(xs[(rbase + g + 8) * PITCH + kt * 8 + t]);
        a[kt][2] = __float_as_uint(xs[(rbase + g) * PITCH + kt * 8 + t + 4]);
        a[kt][3] = __float_as_uint(xs[(rbase + g + 8) * PITCH + kt * 8 + t + 4]);
    }

    const int row_g = row0 + rbase + g;
    float sr  = (row_g < n)     ? g_dinv[row_g]     : 0.f;
    float sr8 = (row_g + 8 < n) ? g_dinv[row_g + 8] : 0.f;

#pragma unroll 4
    for (int nt = 0; nt < 16; nt++) {
        float d0 = 0.f, d1 = 0.f, d2 = 0.f, d3 = 0.f;
#pragma unroll
        for (int kt = 0; kt < 16; kt++) {
            unsigned b0 = __float_as_uint(Wt[(nt * 8 + g) * PITCH + kt * 8 + t]);
            unsigned b1 = __float_as_uint(Wt[(nt * 8 + g) * PITCH + kt * 8 + t + 4]);
            asm volatile(
                "mma.sync.aligned.m16n8k8.row.col.f32.tf32.tf32.f32 "
                "{%0,%1,%2,%3}, {%4,%5,%6,%7}, {%8,%9}, {%0,%1,%2,%3};"
                : "+f"(d0), "+f"(d1), "+f"(d2), "+f"(d3)
                : "r"(a[kt][0]), "r"(a[kt][1]), "r"(a[kt][2]), "r"(a[kt][3]),
                  "r"(b0), "r"(b1));
        }
        __half2 h01 = __floats2half2_rn(d0 * sr, d1 * sr);
        __half2 h23 = __floats2half2_rn(d2 * sr8, d3 * sr8);
        if (row_g < n)
            g_h16[(long long)row_g * 64 + nt * 4 + t] = h01;
        if (row_g + 8 < n)
            g_h16[(long long)(row_g + 8) * 64 + nt * 4 + t] = h23;
    }
}

// ---------------------------------------------------------------------------
// Aggregate: one warp per dst node; out = (sum_edges h16s[src] + h16s[node])*dd + b
__global__ __launch_bounds__(256) void k_agg(const float* __restrict__ bias,
                                             float* __restrict__ out, int n) {
    int node = blockIdx.x * 8 + (threadIdx.x >> 5);
    if (node >= n) return;
    int lane = threadIdx.x & 31;

    const uint2* h = (const uint2*)g_h16;  // 4 halfs / lane / row
    float dd = g_dinv[node];

    float4 acc;
    {
        uint2 sv = h[(long long)node * 32 + lane];
        float2 f0 = __half22float2(*(__half2*)&sv.x);
        float2 f1 = __half22float2(*(__half2*)&sv.y);
        acc.x = f0.x; acc.y = f0.y; acc.z = f1.x; acc.w = f1.y;
    }

    int j = g_start[node];
    int end = j + g_cnt[node];

    for (; j + 3 < end; j += 4) {
        int s0 = g_esrc[j], s1 = g_esrc[j + 1];
        int s2 = g_esrc[j + 2], s3 = g_esrc[j + 3];
        uint2 v0 = h[(long long)s0 * 32 + lane];
        uint2 v1 = h[(long long)s1 * 32 + lane];
        uint2 v2 = h[(long long)s2 * 32 + lane];
        uint2 v3 = h[(long long)s3 * 32 + lane];
#pragma unroll
        for (int q = 0; q < 4; q++) {
            uint2 v = (q == 0) ? v0 : (q == 1) ? v1 : (q == 2) ? v2 : v3;
            float2 f0 = __half22float2(*(__half2*)&v.x);
            float2 f1 = __half22float2(*(__half2*)&v.y);
            acc.x += f0.x; acc.y += f0.y; acc.z += f1.x; acc.w += f1.y;
        }
    }
    for (; j < end; j++) {
        int s = g_esrc[j];
        uint2 v = h[(long long)s * 32 + lane];
        float2 f0 = __half22float2(*(__half2*)&v.x);
        float2 f1 = __half22float2(*(__half2*)&v.y);
        acc.x += f0.x; acc.y += f0.y; acc.z += f1.x; acc.w += f1.y;
    }

    float4 bv = ((const float4*)bias)[lane];
    float4 o;
    o.x = acc.x * dd + bv.x;
    o.y = acc.y * dd + bv.y;
    o.z = acc.z * dd + bv.z;
    o.w = acc.w * dd + bv.w;
    ((float4*)out)[(long long)node * 32 + lane] = o;
}

// ---------------------------------------------------------------------------
extern "C" void kernel_launch(void* const* d_in, const int* in_sizes, int n_in,
                              void* d_out, int out_size) {
    const float* x  = (const float*)d_in[0];
    const int*   ei = (const int*)d_in[1];
    const float* W  = (const float*)d_in[3];
    const float* b  = (const float*)d_in[4];
    float* out = (float*)d_out;

    int n = in_sizes[0] / F;
    int e = in_sizes[1] / 2;
    const int* src = ei;
    const int* dst = ei + e;

    int nblk = (n + SCAN_CHUNK - 1) / SCAN_CHUNK;

    k_zero <<<(n + 255) / 256, 256>>>(n);
    k_hist <<<(e + 255) / 256, 256>>>(dst, e);
    k_scan1<<<nblk, SCAN_CHUNK>>>(n);
    k_scan2<<<1, 512>>>(nblk);
    k_scan3<<<nblk, SCAN_CHUNK>>>(n);      // -> dinv ready
    k_fill <<<(e + 255) / 256, 256>>>(src, dst, e);

    static bool attr_done = false;
    int smem = 2 * 128 * PITCH * (int)sizeof(float);   // 135 KB
    if (!attr_done) {
        cudaFuncSetAttribute(k_gemm, cudaFuncAttributeMaxDynamicSharedMemorySize,
                             smem);
        attr_done = true;
    }
    k_gemm<<<(n + 127) / 128, 256, smem>>>(x, W, n);

    k_agg<<<(n + 7) / 8, 256>>>(b, out, n);
}